// round 1
// baseline (speedup 1.0000x reference)
#include <cuda_runtime.h>
#include <math.h>

// Problem constants (fixed by the dataset)
#define Bsz      8
#define Qlen     2048
#define Klen     2048
#define Hdim     128
#define BM       64     // query tile per CTA
#define BN       64     // key tile per iteration
#define SSTR     68     // smem row stride (floats): mult of 4 (float4 align), not mult of 32
#define NTHREADS 256

#define SMEM_FLOATS (2 * Hdim * SSTR + BM * SSTR + 2 * BM)
#define SMEM_BYTES  (SMEM_FLOATS * 4)

__global__ __launch_bounds__(NTHREADS, 2)
void attn_fp32_flash(const float* __restrict__ out_state,
                     const float* __restrict__ history,
                     float* __restrict__ out)
{
    extern __shared__ float sm[];
    float* Qt      = sm;                    // [Hdim][SSTR]  tanh(Q) transposed
    float* Kt      = Qt + Hdim * SSTR;      // [Hdim][SSTR]  K tile transposed (also V^T)
    float* Ps      = Kt + Hdim * SSTR;      // [BM][SSTR]    unnormalized probs, row-major
    float* alpha_s = Ps + BM * SSTR;        // [BM]
    float* l_s     = alpha_s + BM;          // [BM]

    const int t  = threadIdx.x;
    const int tx = t & 15;                  // 0..15
    const int ty = t >> 4;                  // 0..15
    const int q0 = blockIdx.x * BM;
    const int b  = blockIdx.y;

    const float* q_g = out_state + (size_t)b * Qlen * Hdim;
    const float* h_g = history   + (size_t)b * Klen * Hdim;
    float*       o_g = out       + (size_t)b * Qlen * Hdim;

    // ---- Load Q tile transposed into smem, applying tanh ----
    {
        const int c  = t & 63;              // query row within tile
        const int hb = (t >> 6) * 4;        // 0,4,8,12
        #pragma unroll
        for (int it = 0; it < 8; ++it) {
            const int h = hb + it * 16;
            float4 v = *(const float4*)(q_g + (size_t)(q0 + c) * Hdim + h);
            Qt[(h + 0) * SSTR + c] = tanhf(v.x);
            Qt[(h + 1) * SSTR + c] = tanhf(v.y);
            Qt[(h + 2) * SSTR + c] = tanhf(v.z);
            Qt[(h + 3) * SSTR + c] = tanhf(v.w);
        }
    }

    // O accumulator, stored TRANSPOSED: o[i][j] = O^T[h = ty*8+i][r = tx*4+j]
    float o[8][4];
    #pragma unroll
    for (int i = 0; i < 8; ++i)
        #pragma unroll
        for (int j = 0; j < 4; ++j) o[i][j] = 0.f;

    // running softmax state for rows r = ty*4+i (replicated across the 16 tx threads)
    float mrun[4], lrun[4];
    #pragma unroll
    for (int i = 0; i < 4; ++i) { mrun[i] = -INFINITY; lrun[i] = 0.f; }

    for (int k0 = 0; k0 < Klen; k0 += BN) {
        __syncthreads();   // previous PV done reading Kt/Ps; Qt ready on first iter

        // ---- Load K tile transposed ----
        {
            const int c  = t & 63;
            const int hb = (t >> 6) * 4;
            #pragma unroll
            for (int it = 0; it < 8; ++it) {
                const int h = hb + it * 16;
                float4 v = *(const float4*)(h_g + (size_t)(k0 + c) * Hdim + h);
                Kt[(h + 0) * SSTR + c] = v.x;
                Kt[(h + 1) * SSTR + c] = v.y;
                Kt[(h + 2) * SSTR + c] = v.z;
                Kt[(h + 3) * SSTR + c] = v.w;
            }
        }
        __syncthreads();

        // ---- Scores: S[ty*4+i][tx*4+j] = sum_h Qt[h][ty*4+i] * Kt[h][tx*4+j] ----
        float s[4][4];
        #pragma unroll
        for (int i = 0; i < 4; ++i)
            #pragma unroll
            for (int j = 0; j < 4; ++j) s[i][j] = 0.f;

        #pragma unroll 4
        for (int h = 0; h < Hdim; ++h) {
            float4 qv = *(const float4*)(Qt + h * SSTR + ty * 4);
            float4 kv = *(const float4*)(Kt + h * SSTR + tx * 4);
            s[0][0] += qv.x * kv.x; s[0][1] += qv.x * kv.y; s[0][2] += qv.x * kv.z; s[0][3] += qv.x * kv.w;
            s[1][0] += qv.y * kv.x; s[1][1] += qv.y * kv.y; s[1][2] += qv.y * kv.z; s[1][3] += qv.y * kv.w;
            s[2][0] += qv.z * kv.x; s[2][1] += qv.z * kv.y; s[2][2] += qv.z * kv.z; s[2][3] += qv.z * kv.w;
            s[3][0] += qv.w * kv.x; s[3][1] += qv.w * kv.y; s[3][2] += qv.w * kv.z; s[3][3] += qv.w * kv.w;
        }

        // ---- Online softmax update (reduce across the 16 tx lanes sharing a row) ----
        #pragma unroll
        for (int i = 0; i < 4; ++i) {
            float tm = fmaxf(fmaxf(s[i][0], s[i][1]), fmaxf(s[i][2], s[i][3]));
            #pragma unroll
            for (int m = 1; m < 16; m <<= 1)
                tm = fmaxf(tm, __shfl_xor_sync(0xffffffffu, tm, m));
            const float mnew = fmaxf(mrun[i], tm);
            const float a    = __expf(mrun[i] - mnew);   // exp(-inf)=0 on first tile
            mrun[i] = mnew;

            float rs = 0.f;
            #pragma unroll
            for (int j = 0; j < 4; ++j) { s[i][j] = __expf(s[i][j] - mnew); rs += s[i][j]; }
            #pragma unroll
            for (int m = 1; m < 16; m <<= 1)
                rs += __shfl_xor_sync(0xffffffffu, rs, m);
            lrun[i] = lrun[i] * a + rs;

            if (tx == 0) alpha_s[ty * 4 + i] = a;
            *(float4*)(Ps + (ty * 4 + i) * SSTR + tx * 4) =
                make_float4(s[i][0], s[i][1], s[i][2], s[i][3]);
        }
        __syncthreads();

        // ---- PV: O^T[h][r] = O^T[h][r]*alpha[r] + sum_k Kt[h][k] * Ps[r][k] ----
        #pragma unroll
        for (int j = 0; j < 4; ++j) {
            const float a = alpha_s[tx * 4 + j];
            #pragma unroll
            for (int i = 0; i < 8; ++i) o[i][j] *= a;
        }

        #pragma unroll 4
        for (int k = 0; k < BN; k += 4) {
            float4 pv[4];
            #pragma unroll
            for (int j = 0; j < 4; ++j)
                pv[j] = *(const float4*)(Ps + (tx * 4 + j) * SSTR + k);
            #pragma unroll
            for (int i = 0; i < 8; ++i) {
                float4 kv = *(const float4*)(Kt + (ty * 8 + i) * SSTR + k);
                #pragma unroll
                for (int j = 0; j < 4; ++j) {
                    o[i][j] += kv.x * pv[j].x;
                    o[i][j] += kv.y * pv[j].y;
                    o[i][j] += kv.z * pv[j].z;
                    o[i][j] += kv.w * pv[j].w;
                }
            }
        }
    }

    // ---- Epilogue: publish l, normalize, write out ----
    if (tx == 0) {
        #pragma unroll
        for (int i = 0; i < 4; ++i) l_s[ty * 4 + i] = lrun[i];
    }
    __syncthreads();

    #pragma unroll
    for (int j = 0; j < 4; ++j) {
        const int r = tx * 4 + j;
        const float inv = 1.0f / l_s[r];
        float4 v0 = make_float4(o[0][j] * inv, o[1][j] * inv, o[2][j] * inv, o[3][j] * inv);
        float4 v1 = make_float4(o[4][j] * inv, o[5][j] * inv, o[6][j] * inv, o[7][j] * inv);
        float* dst = o_g + (size_t)(q0 + r) * Hdim + ty * 8;
        *(float4*)(dst)     = v0;
        *(float4*)(dst + 4) = v1;
    }
}

extern "C" void kernel_launch(void* const* d_in, const int* in_sizes, int n_in,
                              void* d_out, int out_size)
{
    const float* out_state = (const float*)d_in[0];
    const float* history   = (const float*)d_in[1];
    float*       out       = (float*)d_out;

    cudaFuncSetAttribute(attn_fp32_flash,
                         cudaFuncAttributeMaxDynamicSharedMemorySize, SMEM_BYTES);

    dim3 grid(Qlen / BM, Bsz);
    attn_fp32_flash<<<grid, NTHREADS, SMEM_BYTES>>>(out_state, history, out);
}

// round 3
// speedup vs baseline: 6.1484x; 6.1484x over previous
#include <cuda_runtime.h>
#include <cuda_fp16.h>
#include <stdint.h>
#include <math.h>

// Problem constants (fixed by dataset)
#define Bsz  8
#define Qlen 2048
#define Klen 2048
#define Hdim 128
#define BM   64          // queries per CTA
#define BN   64          // keys per tile
#define KSTR 272         // smem row stride in bytes (136 halves) -> conflict-free ldmatrix
#define NT   128         // 4 warps

__device__ __forceinline__ uint32_t smem_u32(const void* p) {
    uint32_t a;
    asm("{ .reg .u64 t; cvta.to.shared.u64 t, %1; cvt.u32.u64 %0, t; }" : "=r"(a) : "l"(p));
    return a;
}
__device__ __forceinline__ uint32_t h2u(__half2 h) { return *reinterpret_cast<uint32_t*>(&h); }

// fp32 pair -> fp16 hi + fp16 residual(lo), packed half2
__device__ __forceinline__ void split_h2(float x, float y, uint32_t& hi, uint32_t& lo) {
    __half2 h = __floats2half2_rn(x, y);
    float rx = x - __half2float(__low2half(h));
    float ry = y - __half2float(__high2half(h));
    __half2 l = __floats2half2_rn(rx, ry);
    hi = h2u(h); lo = h2u(l);
}

__device__ __forceinline__ void ldsm_x4(uint32_t& r0, uint32_t& r1, uint32_t& r2, uint32_t& r3,
                                        uint32_t addr) {
    asm volatile("ldmatrix.sync.aligned.m8n8.x4.shared.b16 {%0,%1,%2,%3}, [%4];"
                 : "=r"(r0), "=r"(r1), "=r"(r2), "=r"(r3) : "r"(addr));
}
__device__ __forceinline__ void ldsm_x4_t(uint32_t& r0, uint32_t& r1, uint32_t& r2, uint32_t& r3,
                                          uint32_t addr) {
    asm volatile("ldmatrix.sync.aligned.m8n8.x4.trans.shared.b16 {%0,%1,%2,%3}, [%4];"
                 : "=r"(r0), "=r"(r1), "=r"(r2), "=r"(r3) : "r"(addr));
}
// D(16x8,f32) += A(16x16,f16) * B(16x8,f16)
__device__ __forceinline__ void mma16816(float* d, const uint32_t* a, uint32_t b0, uint32_t b1) {
    asm volatile("mma.sync.aligned.m16n8k16.row.col.f32.f16.f16.f32 "
                 "{%0,%1,%2,%3}, {%4,%5,%6,%7}, {%8,%9}, {%0,%1,%2,%3};"
                 : "+f"(d[0]), "+f"(d[1]), "+f"(d[2]), "+f"(d[3])
                 : "r"(a[0]), "r"(a[1]), "r"(a[2]), "r"(a[3]), "r"(b0), "r"(b1));
}

__global__ __launch_bounds__(NT, 2)
void attn_hmma(const float* __restrict__ out_state,
               const float* __restrict__ history,
               float* __restrict__ out)
{
    // K tile (fp16 hi) + (fp16 lo), rows = 64 keys, 128 h each, stride 272B
    __shared__ __align__(16) char smb[2 * BN * KSTR];
    const uint32_t s_hi = smem_u32(smb);
    const uint32_t s_lo = s_hi + BN * KSTR;

    const int t    = threadIdx.x;
    const int wm   = t >> 5;          // warp id = query-row group
    const int lane = t & 31;
    const int g    = lane >> 2;       // row within fragment group (0..7)
    const int tc   = lane & 3;        // col pair within group
    const int q0   = blockIdx.x * BM;
    const int b    = blockIdx.y;

    const float* q_g = out_state + (size_t)b * Qlen * Hdim;
    const float* h_g = history   + (size_t)b * Klen * Hdim;
    float*       o_g = out       + (size_t)b * Qlen * Hdim;

    // ---- Q A-fragments in registers: rows wm*16+g and +8, split fp16 hi/lo ----
    uint32_t qhi[8][4], qlo[8][4];
    {
        const float* qb = q_g + (size_t)(q0 + wm * 16 + g) * Hdim;
        #pragma unroll
        for (int kk = 0; kk < 8; ++kk) {
            const int h0 = kk * 16 + tc * 2;
            float2 x00 = *(const float2*)(qb + h0);
            float2 x10 = *(const float2*)(qb + 8 * Hdim + h0);
            float2 x01 = *(const float2*)(qb + h0 + 8);
            float2 x11 = *(const float2*)(qb + 8 * Hdim + h0 + 8);
            x00.x = tanhf(x00.x); x00.y = tanhf(x00.y);
            x10.x = tanhf(x10.x); x10.y = tanhf(x10.y);
            x01.x = tanhf(x01.x); x01.y = tanhf(x01.y);
            x11.x = tanhf(x11.x); x11.y = tanhf(x11.y);
            split_h2(x00.x, x00.y, qhi[kk][0], qlo[kk][0]);
            split_h2(x10.x, x10.y, qhi[kk][1], qlo[kk][1]);
            split_h2(x01.x, x01.y, qhi[kk][2], qlo[kk][2]);
            split_h2(x11.x, x11.y, qhi[kk][3], qlo[kk][3]);
        }
    }

    // O accumulator: 16 h-tiles x 4 f32 (rows g, g+8)
    float o[16][4];
    #pragma unroll
    for (int n = 0; n < 16; ++n)
        #pragma unroll
        for (int j = 0; j < 4; ++j) o[n][j] = 0.f;

    float m0 = -INFINITY, m1 = -INFINITY, l0 = 0.f, l1 = 0.f;

    for (int kt = 0; kt < Klen / BN; ++kt) {
        __syncthreads();   // previous tile's ldmatrix reads done before overwrite

        // ---- Load K tile: fp32 gmem -> fp16 hi/lo smem ----
        {
            const float* hb = h_g + (size_t)kt * BN * Hdim;
            #pragma unroll
            for (int j = 0; j < 16; ++j) {
                const int i   = j * NT + t;
                const int row = i >> 5;
                const int c   = i & 31;
                float4 x = *(const float4*)(hb + (size_t)row * Hdim + c * 4);
                uint32_t hA, lA, hB, lB;
                split_h2(x.x, x.y, hA, lA);
                split_h2(x.z, x.w, hB, lB);
                const int off = row * KSTR + c * 8;
                *(uint2*)(smb + off)             = make_uint2(hA, hB);
                *(uint2*)(smb + BN * KSTR + off) = make_uint2(lA, lB);
            }
        }
        __syncthreads();

        // ---- QK^T: S (16x64 per warp), 3-pass split for fp32 accuracy ----
        float s[8][4];
        #pragma unroll
        for (int n = 0; n < 8; ++n)
            #pragma unroll
            for (int j = 0; j < 4; ++j) s[n][j] = 0.f;

        #pragma unroll
        for (int kk = 0; kk < 8; ++kk) {
            uint32_t bh[4][4], bl[4][4];
            #pragma unroll
            for (int np = 0; np < 4; ++np) {
                const uint32_t row = np * 16 + (lane & 7) + ((lane >> 4) << 3);
                const uint32_t col = kk * 32 + ((lane >> 3) & 1) * 16;
                const uint32_t a   = row * KSTR + col;
                ldsm_x4(bh[np][0], bh[np][1], bh[np][2], bh[np][3], s_hi + a);
                ldsm_x4(bl[np][0], bl[np][1], bl[np][2], bl[np][3], s_lo + a);
            }
            #pragma unroll
            for (int n = 0; n < 8; ++n)
                mma16816(s[n], qhi[kk], bh[n >> 1][(n & 1) * 2], bh[n >> 1][(n & 1) * 2 + 1]);
            #pragma unroll
            for (int n = 0; n < 8; ++n)
                mma16816(s[n], qhi[kk], bl[n >> 1][(n & 1) * 2], bl[n >> 1][(n & 1) * 2 + 1]);
            #pragma unroll
            for (int n = 0; n < 8; ++n)
                mma16816(s[n], qlo[kk], bh[n >> 1][(n & 1) * 2], bh[n >> 1][(n & 1) * 2 + 1]);
        }

        // ---- Online softmax (warp-local: each warp owns the full key range) ----
        float t0 = -INFINITY, t1 = -INFINITY;
        #pragma unroll
        for (int n = 0; n < 8; ++n) {
            t0 = fmaxf(t0, fmaxf(s[n][0], s[n][1]));
            t1 = fmaxf(t1, fmaxf(s[n][2], s[n][3]));
        }
        t0 = fmaxf(t0, __shfl_xor_sync(0xffffffffu, t0, 1));
        t0 = fmaxf(t0, __shfl_xor_sync(0xffffffffu, t0, 2));
        t1 = fmaxf(t1, __shfl_xor_sync(0xffffffffu, t1, 1));
        t1 = fmaxf(t1, __shfl_xor_sync(0xffffffffu, t1, 2));

        const float mn0 = fmaxf(m0, t0), mn1 = fmaxf(m1, t1);
        const float al0 = __expf(m0 - mn0), al1 = __expf(m1 - mn1);
        m0 = mn0; m1 = mn1;

        float rs0 = 0.f, rs1 = 0.f;
        #pragma unroll
        for (int n = 0; n < 8; ++n) {
            s[n][0] = __expf(s[n][0] - mn0);
            s[n][1] = __expf(s[n][1] - mn0);
            s[n][2] = __expf(s[n][2] - mn1);
            s[n][3] = __expf(s[n][3] - mn1);
            rs0 += s[n][0] + s[n][1];
            rs1 += s[n][2] + s[n][3];
        }
        rs0 += __shfl_xor_sync(0xffffffffu, rs0, 1);
        rs0 += __shfl_xor_sync(0xffffffffu, rs0, 2);
        rs1 += __shfl_xor_sync(0xffffffffu, rs1, 1);
        rs1 += __shfl_xor_sync(0xffffffffu, rs1, 2);
        l0 = l0 * al0 + rs0;
        l1 = l1 * al1 + rs1;

        // P A-fragments (fp16; P in [0,1], single-pass PV is accurate enough)
        uint32_t pa[4][4];
        #pragma unroll
        for (int kk = 0; kk < 4; ++kk) {
            pa[kk][0] = h2u(__floats2half2_rn(s[2*kk][0],   s[2*kk][1]));
            pa[kk][1] = h2u(__floats2half2_rn(s[2*kk][2],   s[2*kk][3]));
            pa[kk][2] = h2u(__floats2half2_rn(s[2*kk+1][0], s[2*kk+1][1]));
            pa[kk][3] = h2u(__floats2half2_rn(s[2*kk+1][2], s[2*kk+1][3]));
        }

        // rescale O by alpha
        #pragma unroll
        for (int n = 0; n < 16; ++n) {
            o[n][0] *= al0; o[n][1] *= al0;
            o[n][2] *= al1; o[n][3] *= al1;
        }

        // ---- PV: O += P * V (V = same smem bytes as K-hi, via ldmatrix.trans) ----
        #pragma unroll
        for (int kk = 0; kk < 4; ++kk) {
            #pragma unroll
            for (int hp = 0; hp < 8; ++hp) {
                const uint32_t row = kk * 16 + (lane & 7) + (((lane >> 3) & 1) << 3);
                const uint32_t col = hp * 32 + ((lane >> 4) & 1) * 16;
                uint32_t r0, r1, r2, r3;
                ldsm_x4_t(r0, r1, r2, r3, s_hi + row * KSTR + col);
                mma16816(o[2*hp],     pa[kk], r0, r1);
                mma16816(o[2*hp + 1], pa[kk], r2, r3);
            }
        }
    }

    // ---- Epilogue: normalize and store ----
    const float inv0 = 1.0f / l0;
    const float inv1 = 1.0f / l1;
    float* ob = o_g + (size_t)(q0 + wm * 16 + g) * Hdim;
    #pragma unroll
    for (int n = 0; n < 16; ++n) {
        const int h = n * 8 + tc * 2;
        *(float2*)(ob + h)            = make_float2(o[n][0] * inv0, o[n][1] * inv0);
        *(float2*)(ob + 8 * Hdim + h) = make_float2(o[n][2] * inv1, o[n][3] * inv1);
    }
}

extern "C" void kernel_launch(void* const* d_in, const int* in_sizes, int n_in,
                              void* d_out, int out_size)
{
    const float* out_state = (const float*)d_in[0];
    const float* history   = (const float*)d_in[1];
    float*       out       = (float*)d_out;

    dim3 grid(Qlen / BM, Bsz);
    attn_hmma<<<grid, NT>>>(out_state, history, out);
}

// round 4
// speedup vs baseline: 6.9089x; 1.1237x over previous
#include <cuda_runtime.h>
#include <cuda_fp16.h>
#include <stdint.h>
#include <math.h>

// Problem constants (fixed by dataset)
#define Bsz  8
#define Qlen 2048
#define Klen 2048
#define Hdim 128
#define BM   64          // queries per CTA
#define BN   64          // keys per tile
#define NT   128         // 4 warps
#define NTILE (Klen / BN)

#define KTOT (Bsz * Klen * Hdim)   // 2,097,152 elements

// Pre-split history scratch (fp16 hi + residual lo), row-major [b][key][h]
__device__ __align__(16) __half g_khi[KTOT];
__device__ __align__(16) __half g_klo[KTOT];

// smem tile: 64 rows x 128 fp16 = 16KB (hi) + 16KB (lo); double buffered = 64KB
#define TILE_HI_BYTES 16384
#define TILE_BYTES    32768
#define SMEM_BYTES    (2 * TILE_BYTES)

__device__ __forceinline__ uint32_t smem_u32(const void* p) {
    uint32_t a;
    asm("{ .reg .u64 t; cvta.to.shared.u64 t, %1; cvt.u32.u64 %0, t; }" : "=r"(a) : "l"(p));
    return a;
}
__device__ __forceinline__ uint32_t h2u(__half2 h) { return *reinterpret_cast<uint32_t*>(&h); }

// fp32 pair -> fp16 hi + fp16 residual(lo), packed half2
__device__ __forceinline__ void split_h2(float x, float y, uint32_t& hi, uint32_t& lo) {
    __half2 h = __floats2half2_rn(x, y);
    float rx = x - __half2float(__low2half(h));
    float ry = y - __half2float(__high2half(h));
    __half2 l = __floats2half2_rn(rx, ry);
    hi = h2u(h); lo = h2u(l);
}

// XOR-swizzled tile offset: row in [0,64), bytecol in [0,256), 16B-chunk granularity
__device__ __forceinline__ uint32_t swz(int row, int bytecol) {
    return (uint32_t)(row * 256 + ((((bytecol >> 4) ^ row) & 7) << 4) +
                      (bytecol & 0x180) + (bytecol & 15));
}
// NOTE: chunk index = bytecol>>4 in [0,16). XOR only low 3 bits with row&7 so the
// 128B-half (bit 3 of chunk, i.e. bytecol&0x80) is preserved. Rewritten explicitly:
__device__ __forceinline__ uint32_t swz2(int row, int bytecol) {
    int ch = bytecol >> 4;
    int chs = (ch & 8) | ((ch ^ row) & 7);
    return (uint32_t)(row * 256 + (chs << 4));
}

__device__ __forceinline__ void cpa16(uint32_t dst, const void* src) {
    asm volatile("cp.async.cg.shared.global [%0], [%1], 16;" :: "r"(dst), "l"(src));
}
#define CP_COMMIT() asm volatile("cp.async.commit_group;" ::: "memory")
#define CP_WAIT0()  asm volatile("cp.async.wait_group 0;" ::: "memory")

__device__ __forceinline__ void ldsm_x4(uint32_t& r0, uint32_t& r1, uint32_t& r2, uint32_t& r3,
                                        uint32_t addr) {
    asm volatile("ldmatrix.sync.aligned.m8n8.x4.shared.b16 {%0,%1,%2,%3}, [%4];"
                 : "=r"(r0), "=r"(r1), "=r"(r2), "=r"(r3) : "r"(addr));
}
__device__ __forceinline__ void ldsm_x4_t(uint32_t& r0, uint32_t& r1, uint32_t& r2, uint32_t& r3,
                                          uint32_t addr) {
    asm volatile("ldmatrix.sync.aligned.m8n8.x4.trans.shared.b16 {%0,%1,%2,%3}, [%4];"
                 : "=r"(r0), "=r"(r1), "=r"(r2), "=r"(r3) : "r"(addr));
}
// D(16x8,f32) += A(16x16,f16) * B(16x8,f16)
__device__ __forceinline__ void mma16816(float* d, const uint32_t* a, uint32_t b0, uint32_t b1) {
    asm volatile("mma.sync.aligned.m16n8k16.row.col.f32.f16.f16.f32 "
                 "{%0,%1,%2,%3}, {%4,%5,%6,%7}, {%8,%9}, {%0,%1,%2,%3};"
                 : "+f"(d[0]), "+f"(d[1]), "+f"(d[2]), "+f"(d[3])
                 : "r"(a[0]), "r"(a[1]), "r"(a[2]), "r"(a[3]), "r"(b0), "r"(b1));
}

// ---------------- Pre-pass: split history fp32 -> fp16 hi/lo ----------------
__global__ __launch_bounds__(256)
void prep_split(const float* __restrict__ history)
{
    const size_t i = ((size_t)blockIdx.x * 256 + threadIdx.x) * 8;
    float4 a = *(const float4*)(history + i);
    float4 b = *(const float4*)(history + i + 4);
    uint32_t h[4], l[4];
    split_h2(a.x, a.y, h[0], l[0]);
    split_h2(a.z, a.w, h[1], l[1]);
    split_h2(b.x, b.y, h[2], l[2]);
    split_h2(b.z, b.w, h[3], l[3]);
    *(uint4*)(g_khi + i) = make_uint4(h[0], h[1], h[2], h[3]);
    *(uint4*)(g_klo + i) = make_uint4(l[0], l[1], l[2], l[3]);
}

// ---------------- Main attention kernel ----------------
__global__ __launch_bounds__(NT, 2)
void attn_hmma(const float* __restrict__ out_state,
               float* __restrict__ out)
{
    extern __shared__ __align__(16) char smb[];
    const uint32_t s_base = smem_u32(smb);

    const int t    = threadIdx.x;
    const int wm   = t >> 5;          // warp id = query-row group
    const int lane = t & 31;
    const int g    = lane >> 2;       // row within fragment group (0..7)
    const int tc   = lane & 3;        // col pair within group
    const int q0   = blockIdx.x * BM;
    const int b    = blockIdx.y;

    const float*  q_g  = out_state + (size_t)b * Qlen * Hdim;
    const __half* khiB = g_khi + (size_t)b * Klen * Hdim;
    const __half* kloB = g_klo + (size_t)b * Klen * Hdim;
    float*        o_g  = out + (size_t)b * Qlen * Hdim;

    // ---- Q A-fragments in registers: rows wm*16+g and +8, split fp16 hi/lo ----
    uint32_t qhi[8][4], qlo[8][4];
    {
        const float* qb = q_g + (size_t)(q0 + wm * 16 + g) * Hdim;
        #pragma unroll
        for (int kk = 0; kk < 8; ++kk) {
            const int h0 = kk * 16 + tc * 2;
            float2 x00 = *(const float2*)(qb + h0);
            float2 x10 = *(const float2*)(qb + 8 * Hdim + h0);
            float2 x01 = *(const float2*)(qb + h0 + 8);
            float2 x11 = *(const float2*)(qb + 8 * Hdim + h0 + 8);
            x00.x = tanhf(x00.x); x00.y = tanhf(x00.y);
            x10.x = tanhf(x10.x); x10.y = tanhf(x10.y);
            x01.x = tanhf(x01.x); x01.y = tanhf(x01.y);
            x11.x = tanhf(x11.x); x11.y = tanhf(x11.y);
            split_h2(x00.x, x00.y, qhi[kk][0], qlo[kk][0]);
            split_h2(x10.x, x10.y, qhi[kk][1], qlo[kk][1]);
            split_h2(x01.x, x01.y, qhi[kk][2], qlo[kk][2]);
            split_h2(x11.x, x11.y, qhi[kk][3], qlo[kk][3]);
        }
    }

    // O accumulator: 16 h-tiles x 4 f32 (rows g, g+8)
    float o[16][4];
    #pragma unroll
    for (int n = 0; n < 16; ++n)
        #pragma unroll
        for (int j = 0; j < 4; ++j) o[n][j] = 0.f;

    float m0 = -INFINITY, m1 = -INFINITY, l0 = 0.f, l1 = 0.f;

    // ---- Prefetch tile 0 into buffer 0 ----
    {
        const __half* srcH = khiB;
        const __half* srcL = kloB;
        #pragma unroll
        for (int j = 0; j < 8; ++j) {
            const int idx = j * NT + t;        // 0..1023
            const int row = idx >> 4;
            const int ch  = idx & 15;
            const uint32_t d = s_base + swz2(row, ch << 4);
            cpa16(d,                 srcH + (size_t)row * Hdim + ch * 8);
            cpa16(d + TILE_HI_BYTES, srcL + (size_t)row * Hdim + ch * 8);
        }
        CP_COMMIT();
    }

    for (int kt = 0; kt < NTILE; ++kt) {
        CP_WAIT0();
        __syncthreads();   // tile kt visible to all; all warps done with buf[(kt+1)&1]

        // ---- Prefetch tile kt+1 into the other buffer ----
        if (kt + 1 < NTILE) {
            const uint32_t sb = s_base + ((kt + 1) & 1) * TILE_BYTES;
            const __half* srcH = khiB + (size_t)(kt + 1) * BN * Hdim;
            const __half* srcL = kloB + (size_t)(kt + 1) * BN * Hdim;
            #pragma unroll
            for (int j = 0; j < 8; ++j) {
                const int idx = j * NT + t;
                const int row = idx >> 4;
                const int ch  = idx & 15;
                const uint32_t d = sb + swz2(row, ch << 4);
                cpa16(d,                 srcH + (size_t)row * Hdim + ch * 8);
                cpa16(d + TILE_HI_BYTES, srcL + (size_t)row * Hdim + ch * 8);
            }
            CP_COMMIT();
        }

        const uint32_t s_hi = s_base + (kt & 1) * TILE_BYTES;
        const uint32_t s_lo = s_hi + TILE_HI_BYTES;

        // ---- QK^T: S (16x64 per warp), 3-pass split for fp32 accuracy ----
        float s[8][4];
        #pragma unroll
        for (int n = 0; n < 8; ++n)
            #pragma unroll
            for (int j = 0; j < 4; ++j) s[n][j] = 0.f;

        #pragma unroll
        for (int kk = 0; kk < 8; ++kk) {
            uint32_t bh[4][4], bl[4][4];
            #pragma unroll
            for (int np = 0; np < 4; ++np) {
                const int row = np * 16 + (lane & 7) + ((lane >> 4) << 3);
                const int col = kk * 32 + ((lane >> 3) & 1) * 16;   // bytes
                const uint32_t a = swz2(row, col);
                ldsm_x4(bh[np][0], bh[np][1], bh[np][2], bh[np][3], s_hi + a);
                ldsm_x4(bl[np][0], bl[np][1], bl[np][2], bl[np][3], s_lo + a);
            }
            #pragma unroll
            for (int n = 0; n < 8; ++n)
                mma16816(s[n], qhi[kk], bh[n >> 1][(n & 1) * 2], bh[n >> 1][(n & 1) * 2 + 1]);
            #pragma unroll
            for (int n = 0; n < 8; ++n)
                mma16816(s[n], qhi[kk], bl[n >> 1][(n & 1) * 2], bl[n >> 1][(n & 1) * 2 + 1]);
            #pragma unroll
            for (int n = 0; n < 8; ++n)
                mma16816(s[n], qlo[kk], bh[n >> 1][(n & 1) * 2], bh[n >> 1][(n & 1) * 2 + 1]);
        }

        // ---- Online softmax (warp-local: each warp owns the full key range) ----
        float t0 = -INFINITY, t1 = -INFINITY;
        #pragma unroll
        for (int n = 0; n < 8; ++n) {
            t0 = fmaxf(t0, fmaxf(s[n][0], s[n][1]));
            t1 = fmaxf(t1, fmaxf(s[n][2], s[n][3]));
        }
        t0 = fmaxf(t0, __shfl_xor_sync(0xffffffffu, t0, 1));
        t0 = fmaxf(t0, __shfl_xor_sync(0xffffffffu, t0, 2));
        t1 = fmaxf(t1, __shfl_xor_sync(0xffffffffu, t1, 1));
        t1 = fmaxf(t1, __shfl_xor_sync(0xffffffffu, t1, 2));

        const float mn0 = fmaxf(m0, t0), mn1 = fmaxf(m1, t1);
        const float al0 = __expf(m0 - mn0), al1 = __expf(m1 - mn1);
        m0 = mn0; m1 = mn1;

        float rs0 = 0.f, rs1 = 0.f;
        #pragma unroll
        for (int n = 0; n < 8; ++n) {
            s[n][0] = __expf(s[n][0] - mn0);
            s[n][1] = __expf(s[n][1] - mn0);
            s[n][2] = __expf(s[n][2] - mn1);
            s[n][3] = __expf(s[n][3] - mn1);
            rs0 += s[n][0] + s[n][1];
            rs1 += s[n][2] + s[n][3];
        }
        rs0 += __shfl_xor_sync(0xffffffffu, rs0, 1);
        rs0 += __shfl_xor_sync(0xffffffffu, rs0, 2);
        rs1 += __shfl_xor_sync(0xffffffffu, rs1, 1);
        rs1 += __shfl_xor_sync(0xffffffffu, rs1, 2);
        l0 = l0 * al0 + rs0;
        l1 = l1 * al1 + rs1;

        // P A-fragments (fp16; P in [0,1], single-pass PV is accurate enough)
        uint32_t pa[4][4];
        #pragma unroll
        for (int kk = 0; kk < 4; ++kk) {
            pa[kk][0] = h2u(__floats2half2_rn(s[2*kk][0],   s[2*kk][1]));
            pa[kk][1] = h2u(__floats2half2_rn(s[2*kk][2],   s[2*kk][3]));
            pa[kk][2] = h2u(__floats2half2_rn(s[2*kk+1][0], s[2*kk+1][1]));
            pa[kk][3] = h2u(__floats2half2_rn(s[2*kk+1][2], s[2*kk+1][3]));
        }

        // rescale O by alpha
        #pragma unroll
        for (int n = 0; n < 16; ++n) {
            o[n][0] *= al0; o[n][1] *= al0;
            o[n][2] *= al1; o[n][3] *= al1;
        }

        // ---- PV: O += P * V (V = same smem bytes as K-hi, via ldmatrix.trans) ----
        #pragma unroll
        for (int kk = 0; kk < 4; ++kk) {
            #pragma unroll
            for (int hp = 0; hp < 8; ++hp) {
                const int row = kk * 16 + (lane & 7) + (((lane >> 3) & 1) << 3);
                const int col = hp * 32 + ((lane >> 4) & 1) * 16;   // bytes
                uint32_t r0, r1, r2, r3;
                ldsm_x4_t(r0, r1, r2, r3, s_hi + swz2(row, col));
                mma16816(o[2*hp],     pa[kk], r0, r1);
                mma16816(o[2*hp + 1], pa[kk], r2, r3);
            }
        }
    }

    // ---- Epilogue: normalize and store ----
    const float inv0 = 1.0f / l0;
    const float inv1 = 1.0f / l1;
    float* ob = o_g + (size_t)(q0 + wm * 16 + g) * Hdim;
    #pragma unroll
    for (int n = 0; n < 16; ++n) {
        const int h = n * 8 + tc * 2;
        *(float2*)(ob + h)            = make_float2(o[n][0] * inv0, o[n][1] * inv0);
        *(float2*)(ob + 8 * Hdim + h) = make_float2(o[n][2] * inv1, o[n][3] * inv1);
    }
}

extern "C" void kernel_launch(void* const* d_in, const int* in_sizes, int n_in,
                              void* d_out, int out_size)
{
    const float* out_state = (const float*)d_in[0];
    const float* history   = (const float*)d_in[1];
    float*       out       = (float*)d_out;

    // 1) split history fp32 -> fp16 hi/lo scratch
    prep_split<<<KTOT / 8 / 256, 256>>>(history);

    // 2) fused flash attention on HMMA
    cudaFuncSetAttribute(attn_hmma, cudaFuncAttributeMaxDynamicSharedMemorySize, SMEM_BYTES);
    dim3 grid(Qlen / BM, Bsz);
    attn_hmma<<<grid, NT, SMEM_BYTES>>>(out_state, out);
}